// round 17
// baseline (speedup 1.0000x reference)
#include <cuda_runtime.h>
#include <cuda_bf16.h>
#include <cstdint>
#include <cstddef>

// Problem constants (fixed shapes)
#define NROWS   131072          // B*T = 64*2048
#define CGROUPS 4
#define DSUB    128             // d = D/C
#define KCODES  128
#define DFULL   512

#define ROWS_PER_BLOCK 64
#define THREADS 256             // 8 warps = 2 row-sets (32 rows) x 4 code-quarters (32)
#define TAU     0.8f            // near-tie threshold (~7 sigma of 2-pass approx error)

// bf16 tile rows: 136 bf16 stride (272 B) -> conflict-free ldmatrix
#define TROW    136
#define TROWB   (TROW * 2)                  // 272 bytes
#define XTILE_B (ROWS_PER_BLOCK * TROWB)    // 17408
#define ETILE_B (KCODES * TROWB)            // 34816

// smem layout (BYTE offsets)
#define OFF_XB1   0
#define OFF_EB1   (XTILE_B)                         // 17408  (EB1+EB2 contiguous)
#define OFF_EB2   (XTILE_B + ETILE_B)               // 52224
#define OFF_AUX   (XTILE_B + 2 * ETILE_B)           // 87040
#define OFF_E2S   (OFF_AUX)                         // f32[128]
#define OFF_LOSS  (OFF_AUX + 512)                   // f32[64]
#define OFF_BESTK (OFF_AUX + 768)                   // int[64]
#define OFF_IDXA  (OFF_AUX + 1024)                  // int[64]
#define OFF_FLAGS (OFF_AUX + 1280)                  // int[64]
#define OFF_HBS   (OFF_AUX + 1536)                  // f32[64][4]
#define OFF_HBS2  (OFF_AUX + 2560)                  // f32[64][4]
#define OFF_HBK   (OFF_AUX + 3584)                  // int[64][4]
#define OFF_NFLAG (OFF_AUX + 4608)                  // int
#define SMEM_BYTES (OFF_AUX + 4624)                 // 91664 (2 CTAs/SM)

// global scratch (written by pre_kernel):
//  - e2_g: exact XLA-order squared norms
//  - etimg_g: per-group byte image of the two E smem tiles (hi || lo)
__device__ float e2_g[CGROUPS][KCODES];
__device__ __align__(16) uint4 etimg_g[CGROUPS][2 * ETILE_B / 16];

// ---------------- helpers ----------------
__device__ __forceinline__ uint32_t smem_u32(const void* p) {
    uint32_t a;
    asm("{ .reg .u64 t; cvta.to.shared.u64 t, %1; cvt.u32.u64 %0, t; }"
        : "=r"(a) : "l"(p));
    return a;
}
__device__ __forceinline__ void ldmx4(uint32_t* r, uint32_t addr) {
    asm volatile("ldmatrix.sync.aligned.m8n8.x4.shared.b16 {%0,%1,%2,%3}, [%4];"
                 : "=r"(r[0]), "=r"(r[1]), "=r"(r[2]), "=r"(r[3]) : "r"(addr));
}
__device__ __forceinline__ void mma_bf16(float* c, const uint32_t* a, const uint32_t* b) {
    asm volatile(
        "mma.sync.aligned.m16n8k16.row.col.f32.bf16.bf16.f32 "
        "{%0,%1,%2,%3}, {%4,%5,%6,%7}, {%8,%9}, {%0,%1,%2,%3};"
        : "+f"(c[0]), "+f"(c[1]), "+f"(c[2]), "+f"(c[3])
        : "r"(a[0]), "r"(a[1]), "r"(a[2]), "r"(a[3]), "r"(b[0]), "r"(b[1]));
}
// XLA-style warp row-reduction: strided partials in s, shfl_down tree, sum in lane 0.
__device__ __forceinline__ float xla_warp_tree(float s) {
    s += __shfl_down_sync(0xffffffffu, s, 16);
    s += __shfl_down_sync(0xffffffffu, s, 8);
    s += __shfl_down_sync(0xffffffffu, s, 4);
    s += __shfl_down_sync(0xffffffffu, s, 2);
    s += __shfl_down_sync(0xffffffffu, s, 1);
    return s;
}
__device__ __forceinline__ uint32_t bf2_pack(float a, float b) {
    __nv_bfloat162 p = __halves2bfloat162(__float2bfloat16_rn(a), __float2bfloat16_rn(b));
    return *(uint32_t*)&p;
}

// ---- pre-kernel: split-E tile images + e2_g ----
__global__ __launch_bounds__(256)
void pre_kernel(const float* __restrict__ emb) {
    int b = blockIdx.x;
    int t = threadIdx.x;
    if (b < 64) {
        // build E tile images: one thread per (c, k, d4)
        int idx = b * 256 + t;                 // 0..16383
        int c  = idx >> 12;
        int rem = idx & 4095;
        int k  = rem >> 5, d4 = rem & 31;
        float4 v = *(const float4*)(emb + ((size_t)c * KCODES + k) * DSUB + 4 * d4);
        float h0 = __bfloat162float(__float2bfloat16_rn(v.x));
        float h1 = __bfloat162float(__float2bfloat16_rn(v.y));
        float h2 = __bfloat162float(__float2bfloat16_rn(v.z));
        float h3 = __bfloat162float(__float2bfloat16_rn(v.w));
        uint2 w1, w2;
        w1.x = bf2_pack(v.x, v.y);
        w1.y = bf2_pack(v.z, v.w);
        w2.x = bf2_pack(v.x - h0, v.y - h1);
        w2.y = bf2_pack(v.z - h2, v.w - h3);
        char* img = (char*)etimg_g[c];
        size_t o = (size_t)k * TROWB + 8 * d4;
        *(uint2*)(img + o)           = w1;     // hi tile
        *(uint2*)(img + ETILE_B + o) = w2;     // lo tile
    } else {
        // e2: exact XLA reduce order
        int lane = t & 31;
        int w = (b - 64) * 8 + (t >> 5);       // 0..127
        #pragma unroll
        for (int kk = 0; kk < 4; ++kk) {
            int kidx = w * 4 + kk;             // 0..511
            int c = kidx >> 7, k = kidx & 127;
            const float* er = emb + ((size_t)c * KCODES + k) * DSUB;
            float s = 0.0f;
            #pragma unroll
            for (int i = 0; i < 4; ++i) {
                float v = er[lane + 32 * i];
                s = fmaf(v, v, s);
            }
            s = xla_warp_tree(s);
            if (lane == 0) e2_g[c][k] = s;
        }
    }
}

__global__ __launch_bounds__(THREADS, 2)
void pvq_kernel(const float* __restrict__ inp,
                const float* __restrict__ emb,
                float* __restrict__ out_q,
                float* __restrict__ out_idx,
                float* __restrict__ out_loss,
                int write_aux)
{
    extern __shared__ char sm[];
    float* e2s     = (float*)(sm + OFF_E2S);
    float* lossacc = (float*)(sm + OFF_LOSS);
    int*   bestk   = (int*)(sm + OFF_BESTK);
    int*   idxacc  = (int*)(sm + OFF_IDXA);
    int*   flags   = (int*)(sm + OFF_FLAGS);
    float* hbs     = (float*)(sm + OFF_HBS);
    float* hbs2    = (float*)(sm + OFF_HBS2);
    int*   hbk     = (int*)(sm + OFF_HBK);
    int*   nflag   = (int*)(sm + OFF_NFLAG);

    const uint32_t sb = smem_u32(sm);
    const int t    = threadIdx.x;
    const int lane = t & 31;
    const int warp = t >> 5;               // 8 warps
    const int wm2  = warp & 1;             // 32-row set
    const int wq   = warp >> 1;            // code quarter (32 codes)
    const int row0 = blockIdx.x * ROWS_PER_BLOCK;

    // A-side ldmatrix per-lane address (m16k16, row-major), per m16 tile
    const int rA = (lane & 7) + ((lane >> 3) & 1) * 8;
    const int cA = (lane >> 4);
    const uint32_t aOff = (uint32_t)(wm2 * 32 + rA) * TROWB + cA * 16;
    // B-side ldmatrix.x4 per-lane address (two n8 tiles x two k-halves)
    const int rB = (lane & 7) + ((lane >> 4) << 3);  // code within 16
    const int hB = (lane >> 3) & 1;                  // k half
    const uint32_t bOff = (uint32_t)(wq * 32 + rB) * TROWB + hB * 16;

    if (t < ROWS_PER_BLOCK) { lossacc[t] = 0.0f; idxacc[t] = 0; }

    int powc = KCODES * KCODES * KCODES;   // 128^3, /128 per group

    for (int c = 0; c < CGROUPS; ++c) {
        // ---- E tiles: bulk cp.async copy of precomputed split image ----
        {
            const char* src = (const char*)etimg_g[c];
            #pragma unroll
            for (int i = 0; i < (2 * ETILE_B) / (THREADS * 16); ++i) {  // 17 iters
                uint32_t dst = sb + OFF_EB1 + (uint32_t)(t + i * THREADS) * 16;
                const char* s = src + (size_t)(t + i * THREADS) * 16;
                asm volatile("cp.async.cg.shared.global [%0], [%1], 16;"
                             :: "r"(dst), "l"(s));
            }
            asm volatile("cp.async.commit_group;");
        }
        // ---- stage x hi tile only (no residual pass anymore) ----
        {
            #pragma unroll
            for (int i = 0; i < (ROWS_PER_BLOCK * DSUB / 4) / THREADS; ++i) {  // 8
                int f4 = t + i * THREADS;
                int r = f4 >> 5, d4 = f4 & 31;
                float4 v = *(const float4*)(inp + (size_t)(row0 + r) * DFULL
                                            + c * DSUB + 4 * d4);
                uint2 w1;
                w1.x = bf2_pack(v.x, v.y);
                w1.y = bf2_pack(v.z, v.w);
                *(uint2*)(sm + OFF_XB1 + (size_t)r * TROWB + 8 * d4) = w1;
            }
        }
        if (t < KCODES) e2s[t] = e2_g[c][t];
        if (t == 0) *nflag = 0;

        asm volatile("cp.async.wait_group 0;" ::: "memory");
        __syncthreads();   // tiles + e2s visible

        // ---- HMMA GEMM: 32 rows x 32 codes per warp; 2 passes (x1e1 + x1e2) ----
        float acc[2][4][4];
        #pragma unroll
        for (int mt = 0; mt < 2; ++mt)
            #pragma unroll
            for (int nt = 0; nt < 4; ++nt)
                #pragma unroll
                for (int j = 0; j < 4; ++j) acc[mt][nt][j] = 0.0f;

        const uint32_t a1A = sb + OFF_XB1 + aOff;
        const uint32_t b1A = sb + OFF_EB1 + bOff;
        const uint32_t b2A = sb + OFF_EB2 + bOff;

        #pragma unroll
        for (int kk = 0; kk < 8; ++kk) {
            uint32_t ra1[2][4];
            #pragma unroll
            for (int mt = 0; mt < 2; ++mt)
                ldmx4(ra1[mt], a1A + mt * (16 * TROWB) + kk * 32);
            #pragma unroll
            for (int p = 0; p < 2; ++p) {
                uint32_t rb1[4], rb2[4];
                ldmx4(rb1, b1A + p * (16 * TROWB) + kk * 32);
                ldmx4(rb2, b2A + p * (16 * TROWB) + kk * 32);
                #pragma unroll
                for (int mt = 0; mt < 2; ++mt) {
                    mma_bf16(acc[mt][2 * p],     ra1[mt], rb1);      // x1*e1
                    mma_bf16(acc[mt][2 * p],     ra1[mt], rb2);      // x1*e2
                    mma_bf16(acc[mt][2 * p + 1], ra1[mt], rb1 + 2);  // n tile 1
                    mma_bf16(acc[mt][2 * p + 1], ra1[mt], rb2 + 2);
                }
            }
        }
        __syncthreads();

        // ---- approx scores + per-quarter argmin (x2 dropped: row-constant) ----
        {
            int q = lane & 3;                 // 2-col group
            int g = lane >> 2;                // row-in-16 group 0..7
            #pragma unroll
            for (int mt = 0; mt < 2; ++mt) {
                #pragma unroll
                for (int half = 0; half < 2; ++half) {
                    int row = wm2 * 32 + mt * 16 + g + 8 * half;
                    float bs = __int_as_float(0x7f800000), bs2 = bs;
                    int   bk = 0;
                    #pragma unroll
                    for (int nt = 0; nt < 4; ++nt) {
                        int k0 = wq * 32 + 8 * nt + 2 * q;
                        float s0 = e2s[k0]     - 2.0f * acc[mt][nt][2 * half + 0];
                        float s1 = e2s[k0 + 1] - 2.0f * acc[mt][nt][2 * half + 1];
                        if (s0 < bs) { bs2 = bs; bs = s0; bk = k0; }
                        else if (s0 < bs2) { bs2 = s0; }
                        if (s1 < bs) { bs2 = bs; bs = s1; bk = k0 + 1; }
                        else if (s1 < bs2) { bs2 = s1; }
                    }
                    #pragma unroll
                    for (int off = 1; off <= 2; off <<= 1) {
                        float os  = __shfl_xor_sync(0xffffffffu, bs, off);
                        int   ok  = __shfl_xor_sync(0xffffffffu, bk, off);
                        float os2 = __shfl_xor_sync(0xffffffffu, bs2, off);
                        if (os < bs || (os == bs && ok < bk)) {
                            bs2 = fminf(bs, os2);
                            bs = os; bk = ok;
                        } else {
                            bs2 = fminf(bs2, os);
                        }
                    }
                    if (q == 0) {
                        hbs[row * 4 + wq]  = bs;
                        hbs2[row * 4 + wq] = bs2;
                        hbk[row * 4 + wq]  = bk;
                    }
                }
            }
        }
        __syncthreads();

        // ---- combine quarters (ascending k ranges), final argmin + flagging ----
        if (t < ROWS_PER_BLOCK) {
            float bs = __int_as_float(0x7f800000), bs2 = bs;
            int   bk = 0;
            #pragma unroll
            for (int q = 0; q < 4; ++q) {
                float b  = hbs[t * 4 + q];
                int   k  = hbk[t * 4 + q];
                float s2 = hbs2[t * 4 + q];
                if (b < bs) { bs2 = bs; bs = b; bk = k; }
                else { bs2 = fminf(bs2, b); }
                bs2 = fminf(bs2, s2);
            }
            bestk[t] = bk;
            if (bs2 - bs < TAU) {
                int pos = atomicAdd(nflag, 1);
                flags[pos] = t;
            }
        }
        __syncthreads();

        // ---- exact recheck for flagged rows: 4 warps per row, one k-quarter
        //      each; bit-exact reference math (sequential fmaf, XLA x2) ----
        {
            int nf = *nflag;
            int kb = warp & 3;
            for (int i = (warp >> 2); i < nf; i += 2) {
                int row = flags[i];
                const float* xg = inp + (size_t)(row0 + row) * DFULL + c * DSUB;
                // exact x2 in XLA order (all 4 warps compute identically)
                float s = 0.0f;
                #pragma unroll
                for (int m = 0; m < 4; ++m) {
                    float v = xg[lane + 32 * m];
                    s = fmaf(v, v, s);
                }
                s = xla_warp_tree(s);
                float x2v = __shfl_sync(0xffffffffu, s, 0);
                int k = kb * 32 + lane;
                const float* eg = emb + ((size_t)c * KCODES + k) * DSUB;
                float dt = 0.0f;
                for (int dd = 0; dd < DSUB; ++dd)
                    dt = fmaf(xg[dd], eg[dd], dt);       // sequential, ascending
                float bs = (x2v + e2s[k]) - 2.0f * dt;   // reference rounding
                int   bk = k;
                #pragma unroll
                for (int off = 16; off >= 1; off >>= 1) {
                    float os = __shfl_xor_sync(0xffffffffu, bs, off);
                    int   ok = __shfl_xor_sync(0xffffffffu, bk, off);
                    if (os < bs || (os == bs && ok < bk)) { bs = os; bk = ok; }
                }
                if (lane == 0) {
                    hbs[row * 4 + kb] = bs;
                    hbk[row * 4 + kb] = bk;
                }
            }
        }
        __syncthreads();
        {
            int nf = *nflag;
            if (t < nf) {
                int row = flags[t];
                float bs = __int_as_float(0x7f800000);
                int   bk = 0;
                #pragma unroll
                for (int q = 0; q < 4; ++q) {            // ascending k ranges
                    float b = hbs[row * 4 + q];
                    int   k = hbk[row * 4 + q];
                    if (b < bs) { bs = b; bk = k; }      // strict < keeps smallest k
                }
                bestk[row] = bk;
            }
        }
        __syncthreads();

        // ---- index accumulation + epilogue (quantized_sg, loss) from GLOBAL ----
        if (t < ROWS_PER_BLOCK) idxacc[t] += bestk[t] * powc;
        #pragma unroll
        for (int rr = 0; rr < ROWS_PER_BLOCK / 8; ++rr) {   // 8 rows per warp
            int r = warp * 8 + rr;
            int k = bestk[r];
            const float* eg = emb + ((size_t)c * KCODES + k) * DSUB;
            const float* xg = inp + (size_t)(row0 + r) * DFULL + c * DSUB;
            float* qrow = out_q + (size_t)(row0 + r) * DFULL + c * DSUB;

            float part = 0.0f;
            #pragma unroll
            for (int m = 0; m < 4; ++m) {
                int dd = lane + 32 * m;
                float ev = eg[dd];
                float xv = xg[dd];
                float dlt = ev - xv;
                part = fmaf(dlt, dlt, part);
                qrow[dd] = xv + dlt;                    // x + (q - x), matches ref
            }
            #pragma unroll
            for (int off = 16; off >= 1; off >>= 1)
                part += __shfl_xor_sync(0xffffffffu, part, off);
            if (lane == 0) lossacc[r] += part;
        }
        powc >>= 7;  // /128
        __syncthreads();
    }

    if (write_aux && t < ROWS_PER_BLOCK) {
        int n = row0 + t;
        out_idx[n] = (float)idxacc[t];
        float d2 = lossacc[t];
        out_loss[n] = d2 + 0.25f * d2;   // q_latent + 0.25*e_latent
    }
}

extern "C" void kernel_launch(void* const* d_in, const int* in_sizes, int n_in,
                              void* d_out, int out_size) {
    const float* inp = (const float*)d_in[0];   // inputs (64,2048,512) f32
    const float* emb = (const float*)d_in[1];   // embeddings (4,128,128) f32
    float* out = (float*)d_out;

    const long long QN = (long long)NROWS * DFULL;
    int write_aux = ((long long)out_size >= QN + 2LL * NROWS) ? 1 : 0;
    float* out_q    = out;
    float* out_idx  = out + QN;
    float* out_loss = out + QN + NROWS;

    pre_kernel<<<80, 256>>>(emb);

    cudaFuncSetAttribute(pvq_kernel,
                         cudaFuncAttributeMaxDynamicSharedMemorySize, SMEM_BYTES);
    pvq_kernel<<<NROWS / ROWS_PER_BLOCK, THREADS, SMEM_BYTES>>>(
        inp, emb, out_q, out_idx, out_loss, write_aux);
}